// round 2
// baseline (speedup 1.0000x reference)
#include <cuda_runtime.h>
#include <math.h>

// ---------------------------------------------------------------------------
// GRNNTransformGated: binary-tree GRNN, B=1024, L=10, H=128, FEAT=7.
// Level j has n = 1024*2^j nodes. children are structurally [2i, 2i+1], so
// [h_L | h_R] for node i is rows 2i, 2i+1 of the previous level's emb (contiguous).
//
// Fused per-level kernel: block = 64 nodes (TM), 256 threads.
//   HHU [64 x 384] in smem (cols: 0..127 h_L, 128..255 h_R, 256..383 u)
//   R stage:  A = sigmoid(HHU @ W_r + b_r) * HHU        (K=384, N=384)
//   H stage:  HH = conv3(A @ W_h + b_h)                 (K=384, N=128) -> overwrites A[:, :128]
//   Z stage:  Z = [HH | HHU] @ W_z + b_z                (K=512, N=512)
//             gate layout packed so each thread holds all 4 gate logits per feature,
//             softmax over gates done in registers, output written directly.
// ---------------------------------------------------------------------------

#define TM        64
#define NTHREADS  256
#define SA_STRIDE 385          // 64 rows x 385 (pad 1 to kill bank conflicts on row-indexed reads)
#define SW_STRIDE 132          // 32 rows x (128+4), float4-aligned

// Ping-pong embedding buffers (max level: 524288 nodes x 128 feats)
__device__ float g_embA[524288 * 128];
__device__ float g_embB[524288 * 128];

__device__ __forceinline__ float conv3(float x, float cw, float cb) {
    x = fmaxf(fmaf(cw, x, cb), 0.0f);
    x = fmaxf(fmaf(cw, x, cb), 0.0f);
    x = fmaxf(fmaf(cw, x, cb), 0.0f);
    return x;
}

// ---------------------------------------------------------------------------
// Leaf level (j=9): emb = conv3(contents @ W_u + b_u). 2 nodes per 256-thread block.
// ---------------------------------------------------------------------------
__global__ __launch_bounds__(256, 1)
void leaf_kernel(const float* __restrict__ contents,
                 const float* __restrict__ W_u, const float* __restrict__ b_u,
                 const float* __restrict__ cwp, const float* __restrict__ cbp,
                 float* __restrict__ emb)
{
    const int node = blockIdx.x * 2 + (threadIdx.x >> 7);
    const int h    = threadIdx.x & 127;
    const float cw = cwp[0], cb = cbp[0];
    const float* c = contents + (long long)node * 7;
    float acc = b_u[h];
#pragma unroll
    for (int f = 0; f < 7; ++f)
        acc = fmaf(c[f], W_u[f * 128 + h], acc);
    emb[(long long)node * 128 + h] = conv3(acc, cw, cb);
}

// ---------------------------------------------------------------------------
// Inner level kernel (j < 9). gridDim.x = n / TM.
// ---------------------------------------------------------------------------
__global__ __launch_bounds__(256, 1)
void level_kernel(const float* __restrict__ contents,
                  const float* __restrict__ emb_prev,
                  float* __restrict__ emb_out,
                  const float* __restrict__ W_u, const float* __restrict__ b_u,
                  const float* __restrict__ W_r, const float* __restrict__ b_r,
                  const float* __restrict__ W_h, const float* __restrict__ b_h,
                  const float* __restrict__ W_z, const float* __restrict__ b_z,
                  const float* __restrict__ cwp, const float* __restrict__ cbp)
{
    extern __shared__ float sm[];
    float* s_hhu = sm;                         // [TM][SA_STRIDE]
    float* s_a   = sm + TM * SA_STRIDE;        // [TM][SA_STRIDE]  (A, later HH in cols 0..127)
    float* s_w   = sm + 2 * TM * SA_STRIDE;    // [32][SW_STRIDE]

    const int tid = threadIdx.x;
    const int tc  = tid & 15;     // 0..15 column-thread
    const int tr  = tid >> 4;     // 0..15 row-thread (4 rows each)
    const int m0  = blockIdx.x * TM;
    const float cw = cwp[0], cb = cbp[0];

    // ---- Load h_L | h_R (cols 0..255): contiguous 64x256 slab of emb_prev ----
    {
        const float4* src = (const float4*)(emb_prev + (long long)(2 * m0) * 128);
        for (int q = tid; q < TM * 64; q += NTHREADS) {   // 64 float4 per row
            const int row = q >> 6;
            const int c4  = q & 63;
            float4 v = src[q];
            float* d = s_hhu + row * SA_STRIDE + c4 * 4;
            d[0] = v.x; d[1] = v.y; d[2] = v.z; d[3] = v.w;
        }
    }
    // ---- Compute u into cols 256..383 ----
#pragma unroll
    for (int i = 0; i < 4; ++i) {
        const int row = tr * 4 + i;
        const float* c = contents + (long long)(m0 + row) * 7;
        float cf[7];
#pragma unroll
        for (int f = 0; f < 7; ++f) cf[f] = c[f];
#pragma unroll
        for (int jj = 0; jj < 8; ++jj) {
            const int h = tc * 8 + jj;
            float acc = b_u[h];
#pragma unroll
            for (int f = 0; f < 7; ++f)
                acc = fmaf(cf[f], W_u[f * 128 + h], acc);
            s_hhu[row * SA_STRIDE + 256 + h] = conv3(acc, cw, cb);
        }
    }
    __syncthreads();

    // ======================= R stage: A = sigmoid(HHU@W_r + b_r) * HHU ======
#pragma unroll 1
    for (int n0 = 0; n0 < 384; n0 += 128) {
        float acc[4][8];
#pragma unroll
        for (int i = 0; i < 4; ++i)
#pragma unroll
            for (int j = 0; j < 8; ++j)
                acc[i][j] = b_r[n0 + tc * 8 + j];

#pragma unroll 1
        for (int k0 = 0; k0 < 384; k0 += 32) {
            // stage W_r[k0:k0+32, n0:n0+128]
#pragma unroll
            for (int q = 0; q < 4; ++q) {
                const int id = tid + q * 256;
                const int kk = id >> 5, c4 = id & 31;
                float4 v = *(const float4*)(W_r + (long long)(k0 + kk) * 384 + n0 + c4 * 4);
                *(float4*)(s_w + kk * SW_STRIDE + c4 * 4) = v;
            }
            __syncthreads();
#pragma unroll 8
            for (int kk = 0; kk < 32; ++kk) {
                const float a0 = s_hhu[(tr * 4 + 0) * SA_STRIDE + k0 + kk];
                const float a1 = s_hhu[(tr * 4 + 1) * SA_STRIDE + k0 + kk];
                const float a2 = s_hhu[(tr * 4 + 2) * SA_STRIDE + k0 + kk];
                const float a3 = s_hhu[(tr * 4 + 3) * SA_STRIDE + k0 + kk];
                float4 w0 = *(const float4*)(s_w + kk * SW_STRIDE + tc * 8);
                float4 w1 = *(const float4*)(s_w + kk * SW_STRIDE + tc * 8 + 4);
                const float w[8] = {w0.x, w0.y, w0.z, w0.w, w1.x, w1.y, w1.z, w1.w};
#pragma unroll
                for (int j = 0; j < 8; ++j) {
                    acc[0][j] = fmaf(a0, w[j], acc[0][j]);
                    acc[1][j] = fmaf(a1, w[j], acc[1][j]);
                    acc[2][j] = fmaf(a2, w[j], acc[2][j]);
                    acc[3][j] = fmaf(a3, w[j], acc[3][j]);
                }
            }
            __syncthreads();
        }
        // epilogue: sigmoid, multiply by HHU, write A
#pragma unroll
        for (int i = 0; i < 4; ++i) {
            const int row = tr * 4 + i;
#pragma unroll
            for (int j = 0; j < 8; ++j) {
                const int col = n0 + tc * 8 + j;
                const float r = 1.0f / (1.0f + __expf(-acc[i][j]));
                s_a[row * SA_STRIDE + col] = r * s_hhu[row * SA_STRIDE + col];
            }
        }
    }
    __syncthreads();

    // ======================= H stage: HH = conv3(A @ W_h + b_h) =============
    {
        float acc[4][8];
#pragma unroll
        for (int i = 0; i < 4; ++i)
#pragma unroll
            for (int j = 0; j < 8; ++j)
                acc[i][j] = b_h[tc * 8 + j];

#pragma unroll 1
        for (int k0 = 0; k0 < 384; k0 += 32) {
#pragma unroll
            for (int q = 0; q < 4; ++q) {
                const int id = tid + q * 256;
                const int kk = id >> 5, c4 = id & 31;
                float4 v = *(const float4*)(W_h + (long long)(k0 + kk) * 128 + c4 * 4);
                *(float4*)(s_w + kk * SW_STRIDE + c4 * 4) = v;
            }
            __syncthreads();
#pragma unroll 8
            for (int kk = 0; kk < 32; ++kk) {
                const float a0 = s_a[(tr * 4 + 0) * SA_STRIDE + k0 + kk];
                const float a1 = s_a[(tr * 4 + 1) * SA_STRIDE + k0 + kk];
                const float a2 = s_a[(tr * 4 + 2) * SA_STRIDE + k0 + kk];
                const float a3 = s_a[(tr * 4 + 3) * SA_STRIDE + k0 + kk];
                float4 w0 = *(const float4*)(s_w + kk * SW_STRIDE + tc * 8);
                float4 w1 = *(const float4*)(s_w + kk * SW_STRIDE + tc * 8 + 4);
                const float w[8] = {w0.x, w0.y, w0.z, w0.w, w1.x, w1.y, w1.z, w1.w};
#pragma unroll
                for (int j = 0; j < 8; ++j) {
                    acc[0][j] = fmaf(a0, w[j], acc[0][j]);
                    acc[1][j] = fmaf(a1, w[j], acc[1][j]);
                    acc[2][j] = fmaf(a2, w[j], acc[2][j]);
                    acc[3][j] = fmaf(a3, w[j], acc[3][j]);
                }
            }
            __syncthreads();
        }
        // all reads of A are done (sync above) -> overwrite A[:, 0:128] with HH
#pragma unroll
        for (int i = 0; i < 4; ++i) {
            const int row = tr * 4 + i;
#pragma unroll
            for (int j = 0; j < 8; ++j)
                s_a[row * SA_STRIDE + tc * 8 + j] = conv3(acc[i][j], cw, cb);
        }
    }
    __syncthreads();

    // ======================= Z stage + gated softmax output ==================
    // For feature chunk fc: 32 features x 4 gates packed as 128 cols.
    // Thread owns 2 features (tc*2, tc*2+1), all 4 gates -> local softmax.
#pragma unroll 1
    for (int fc = 0; fc < 4; ++fc) {
        float acc[4][2][4];   // [row][feat][gate]
#pragma unroll
        for (int i = 0; i < 4; ++i)
#pragma unroll
            for (int f = 0; f < 2; ++f)
#pragma unroll
                for (int g = 0; g < 4; ++g)
                    acc[i][f][g] = b_z[g * 128 + fc * 32 + tc * 2 + f];

#pragma unroll 1
        for (int k0 = 0; k0 < 512; k0 += 32) {
            // stage W_z[k0:k0+32, gates x (fc*32..fc*32+31)] packed as [kk][g*32+lc]
#pragma unroll
            for (int q = 0; q < 4; ++q) {
                const int id = tid + q * 256;
                const int kk = id >> 5, p = id & 31;
                const int g = p >> 3, lc = (p & 7) * 4;
                float4 v = *(const float4*)(W_z + (long long)(k0 + kk) * 512 + g * 128 + fc * 32 + lc);
                *(float4*)(s_w + kk * SW_STRIDE + g * 32 + lc) = v;
            }
            __syncthreads();
            const float* abase = (k0 < 128) ? (s_a + k0) : (s_hhu + (k0 - 128));
#pragma unroll 8
            for (int kk = 0; kk < 32; ++kk) {
                const float a0 = abase[(tr * 4 + 0) * SA_STRIDE + kk];
                const float a1 = abase[(tr * 4 + 1) * SA_STRIDE + kk];
                const float a2 = abase[(tr * 4 + 2) * SA_STRIDE + kk];
                const float a3 = abase[(tr * 4 + 3) * SA_STRIDE + kk];
#pragma unroll
                for (int g = 0; g < 4; ++g) {
                    float2 w = *(const float2*)(s_w + kk * SW_STRIDE + g * 32 + tc * 2);
                    acc[0][0][g] = fmaf(a0, w.x, acc[0][0][g]);
                    acc[0][1][g] = fmaf(a0, w.y, acc[0][1][g]);
                    acc[1][0][g] = fmaf(a1, w.x, acc[1][0][g]);
                    acc[1][1][g] = fmaf(a1, w.y, acc[1][1][g]);
                    acc[2][0][g] = fmaf(a2, w.x, acc[2][0][g]);
                    acc[2][1][g] = fmaf(a2, w.y, acc[2][1][g]);
                    acc[3][0][g] = fmaf(a3, w.x, acc[3][0][g]);
                    acc[3][1][g] = fmaf(a3, w.y, acc[3][1][g]);
                }
            }
            __syncthreads();
        }
        // epilogue: softmax over 4 gates, combine, write out
#pragma unroll
        for (int i = 0; i < 4; ++i) {
            const int row = tr * 4 + i;
#pragma unroll
            for (int f = 0; f < 2; ++f) {
                const int c = fc * 32 + tc * 2 + f;
                const float z0 = acc[i][f][0], z1 = acc[i][f][1];
                const float z2 = acc[i][f][2], z3 = acc[i][f][3];
                const float mx = fmaxf(fmaxf(z0, z1), fmaxf(z2, z3));
                const float e0 = __expf(z0 - mx), e1 = __expf(z1 - mx);
                const float e2 = __expf(z2 - mx), e3 = __expf(z3 - mx);
                const float inv = 1.0f / (e0 + e1 + e2 + e3);
                const float hH = s_a[row * SA_STRIDE + c];
                const float hL = s_hhu[row * SA_STRIDE + c];
                const float hR = s_hhu[row * SA_STRIDE + 128 + c];
                const float uu = s_hhu[row * SA_STRIDE + 256 + c];
                emb_out[(long long)(m0 + row) * 128 + c] =
                    (e0 * hH + e1 * hL + e2 * hR + e3 * uu) * inv;
            }
        }
    }
}

// ---------------------------------------------------------------------------
// Host launcher
// ---------------------------------------------------------------------------
extern "C" void kernel_launch(void* const* d_in, const int* in_sizes, int n_in,
                              void* d_out, int out_size)
{
    const float* contents = (const float*)d_in[0];
    // d_in[1] = children (int32) — structurally [2i, 2i+1]; not needed.
    const float* W_u = (const float*)d_in[2];
    const float* b_u = (const float*)d_in[3];
    const float* W_h = (const float*)d_in[4];
    const float* b_h = (const float*)d_in[5];
    const float* W_z = (const float*)d_in[6];
    const float* b_z = (const float*)d_in[7];
    const float* W_r = (const float*)d_in[8];
    const float* b_r = (const float*)d_in[9];
    const float* cw  = (const float*)d_in[10];
    const float* cb  = (const float*)d_in[11];

    float *embA, *embB;
    cudaGetSymbolAddress((void**)&embA, g_embA);
    cudaGetSymbolAddress((void**)&embB, g_embB);

    const int smem = (2 * TM * SA_STRIDE + 32 * SW_STRIDE) * (int)sizeof(float);
    cudaFuncSetAttribute(level_kernel, cudaFuncAttributeMaxDynamicSharedMemorySize, smem);

    // Level 9 (leaves)
    {
        const long long off9 = 1024LL * ((1LL << 9) - 1);
        const int n9 = 1024 << 9;
        leaf_kernel<<<n9 / 2, 256>>>(contents + off9 * 7, W_u, b_u, cw, cb, embA);
    }

    const float* prev = embA;
    for (int j = 8; j >= 0; --j) {
        const long long off = 1024LL * ((1LL << j) - 1);
        const int n = 1024 << j;
        float* outp = (j == 0) ? (float*)d_out : ((prev == embA) ? embB : embA);
        level_kernel<<<n / TM, NTHREADS, smem>>>(
            contents + off * 7, prev, outp,
            W_u, b_u, W_r, b_r, W_h, b_h, W_z, b_z, cw, cb);
        prev = outp;
    }
}